// round 9
// baseline (speedup 1.0000x reference)
#include <cuda_runtime.h>
#include <cuda_bf16.h>

// Problem constants
#define NB 4
#define NC 64
#define NH 128
#define NW 128
#define NN 16
#define NPIX (NB*NH*NW)   // 65536 pixels

typedef unsigned long long u64;

// Scratch (allocation-free rule: __device__ globals)
static __device__ float g_delta[(size_t)NPIX*64];   // [p][c]
static __device__ float g_u[(size_t)NPIX*64];       // [p][c]
static __device__ float g_Bc[(size_t)NPIX*16];      // [p][n]
static __device__ float g_Cc[(size_t)NPIX*16];      // [p][n]
static __device__ float g_yh[(size_t)NPIX*64];      // [p][c]
static __device__ float g_yv[(size_t)NPIX*64];      // [p][c]

__device__ __forceinline__ float fexp2(float x) {
    float r;
    asm("ex2.approx.f32 %0, %1;" : "=f"(r) : "f"(x));
    return r;
}
__device__ __forceinline__ u64 pack2(float lo, float hi) {
    u64 r; asm("mov.b64 %0, {%1, %2};" : "=l"(r) : "f"(lo), "f"(hi)); return r;
}
__device__ __forceinline__ void unpack2(u64 v, float& lo, float& hi) {
    asm("mov.b64 {%0, %1}, %2;" : "=f"(lo), "=f"(hi) : "l"(v));
}
__device__ __forceinline__ u64 fma2(u64 a, u64 b, u64 c) {
    u64 d; asm("fma.rn.f32x2 %0, %1, %2, %3;" : "=l"(d) : "l"(a), "l"(b), "l"(c)); return d;
}
__device__ __forceinline__ u64 mul2(u64 a, u64 b) {
    u64 d; asm("mul.rn.f32x2 %0, %1, %2;" : "=l"(d) : "l"(a), "l"(b)); return d;
}

// ---------------------------------------------------------------------------
// Projection v5: grid = 512 rows x 2 output-halves; 128-thread blocks sized
// for 7 resident blocks/SM => grid 1024 fits in ONE wave (no tail).
// Block (bh, og) computes outputs [48*og, 48*og+48) for 128 pixels.
// Thread (ty 0..7, tx 0..15): 6 outs x 4 pixel-pairs = 24 packed f32x2 accs.
// ---------------------------------------------------------------------------
#define WT_STRIDE 52    // s_wt row pad ([k][48 outs])
#define X_STRIDE  130   // s_x  row pad ([k][128 pix]), even => 8B aligned

__global__ __launch_bounds__(128, 7) void proj_kernel(const float* __restrict__ x,
                                                      const float* __restrict__ xw,   // [36,64]
                                                      const float* __restrict__ dtw,  // [64,4]
                                                      const float* __restrict__ dtb)  // [64]
{
    __shared__ __align__(16) float s_wt[64*WT_STRIDE];  // [k 0..63][o_local]; reused as staging
    __shared__ __align__(16) float s_x[32*X_STRIDE];    // [k-half][pix]
    __shared__ float s_bias[64];

    int blk = blockIdx.x;          // 0..1023
    int bh  = blk >> 1;            // row 0..511
    int og  = blk & 1;             // output half
    int b   = bh >> 7;
    int h   = bh & 127;
    int tid = threadIdx.x;
    int tx  = tid & 15;            // pixel-pair group
    int ty  = tid >> 4;            // 0..7

    // Fold weights for this block's 48 output rows, stored [k][o_local].
    for (int i = tid; i < 48*64; i += 128) {
        int rl = i >> 6, c = i & 63;
        int r  = og*48 + rl;
        float v;
        if (r < 64) {
            v = dtw[r*4+0]*xw[0*64+c] + dtw[r*4+1]*xw[1*64+c]
              + dtw[r*4+2]*xw[2*64+c] + dtw[r*4+3]*xw[3*64+c];
        } else {
            v = xw[(r - 60)*64 + c];
        }
        s_wt[c*WT_STRIDE + rl] = v;
    }
    if (tid < 64) s_bias[tid] = dtb[tid];

    size_t pbase = (size_t)bh * 128;

    u64 acc2[6][4];
    #pragma unroll
    for (int i = 0; i < 6; i++)
        #pragma unroll
        for (int jp = 0; jp < 4; jp++) acc2[i][jp] = 0ull;

    for (int half = 0; half < 2; half++) {
        __syncthreads();   // half 0: also covers weight-fold completion
        // Load x tile: 32 channels x 128 pixels, coalesced rows
        #pragma unroll
        for (int it = 0; it < 32; it++) {
            int idx = it*128 + tid;
            int cl  = idx >> 7;      // 0..31
            int w   = idx & 127;
            s_x[cl*X_STRIDE + w] =
                x[(((size_t)(b*64 + half*32 + cl))*128 + h)*128 + w];
        }
        __syncthreads();

        // og==0 block also emits the u transpose [p][c] (coalesced 128B rows)
        if (og == 0) {
            #pragma unroll
            for (int it = 0; it < 32; it++) {
                int idx = it*128 + tid;
                int pix = idx >> 5;
                int c   = idx & 31;
                g_u[(pbase + pix)*64 + half*32 + c] = s_x[c*X_STRIDE + pix];
            }
        }

        // GEMM mainloop over this half's 32 channels (weight rows half*32+k)
        #pragma unroll 4
        for (int k = 0; k < 32; k++) {
            const float* wrow = s_wt + (half*32 + k)*WT_STRIDE + ty;
            u64 w2[6];
            #pragma unroll
            for (int i = 0; i < 6; i++) {
                float wv = wrow[8*i];
                w2[i] = pack2(wv, wv);
            }
            u64 xp[4];
            #pragma unroll
            for (int jp = 0; jp < 4; jp++)
                xp[jp] = *(const u64*)(s_x + k*X_STRIDE + 2*tx + 32*jp);
            #pragma unroll
            for (int i = 0; i < 6; i++)
                #pragma unroll
                for (int jp = 0; jp < 4; jp++)
                    acc2[i][jp] = fma2(w2[i], xp[jp], acc2[i][jp]);
        }
    }

    __syncthreads();

    // Epilogue: 3 chunks of 16 outputs; stage [pix][j] in smem (reuse s_wt).
    float* s_st = s_wt;
    for (int cch = 0; cch < 3; cch++) {
        #pragma unroll
        for (int jp = 0; jp < 4; jp++) {
            #pragma unroll
            for (int ii = 0; ii < 2; ii++) {
                float lo, hi; unpack2(acc2[cch*2 + ii][jp], lo, hi);
                int pp = 2*tx + 32*jp;
                s_st[pp*17 + ty + 8*ii]       = lo;
                s_st[(pp + 1)*17 + ty + 8*ii] = hi;
            }
        }
        __syncthreads();
        #pragma unroll
        for (int it = 0; it < 16; it++) {
            int idx = it*128 + tid;
            int pix = idx >> 4;
            int j   = idx & 15;
            float v = s_st[pix*17 + j];
            int o   = og*48 + cch*16 + j;
            if (o < 64) {
                v += s_bias[o];
                v = (v > 15.f) ? v : __logf(1.f + __expf(v));   // softplus
                g_delta[(pbase + pix)*64 + o] = v;
            } else if (o < 80) {
                g_Bc[(pbase + pix)*16 + (o - 64)] = v;
            } else {
                g_Cc[(pbase + pix)*16 + (o - 80)] = v;
            }
        }
        __syncthreads();
    }
}

// ---------------------------------------------------------------------------
// Scan v4: thread = (sequence, channel d, quarter q of 16 states).
// 256-thread blocks (64 ch x 4 quarters), 1024 blocks (512 H + 512 V).
// 4 states/thread: 2 packed f32x2 accumulators, 4 ex2/iter, 2-level shfl.
// ---------------------------------------------------------------------------
__global__ __launch_bounds__(256) void scan_kernel(const float* __restrict__ A_log)
{
    int tid  = threadIdx.x;
    int d    = tid >> 2;          // channel 0..63
    int q    = tid & 3;           // state quarter (states 4q..4q+3)
    int blk  = blockIdx.x;        // 0..1023
    int dir  = blk >> 9;          // 0 = H, 1 = V
    int s    = blk & 511;
    int b    = s >> 7;
    int rc   = s & 127;

    size_t pix0;
    int stride;
    float* __restrict__ yout;
    if (dir == 0) { pix0 = ((size_t)(b*128 + rc))*128; stride = 1;   yout = g_yh; }
    else          { pix0 = (size_t)b*16384 + rc;       stride = 128; yout = g_yv; }

    u64 A22[2];
    #pragma unroll
    for (int t = 0; t < 2; t++) {
        const float* ap = A_log + d*16 + q*4 + 2*t;
        float a0 = -__expf(ap[0]) * 1.4426950408889634f;
        float a1 = -__expf(ap[1]) * 1.4426950408889634f;
        A22[t] = pack2(a0, a1);
    }

    u64 hs2[2];
    hs2[0] = 0ull; hs2[1] = 0ull;

    size_t p = pix0;

    float delta = g_delta[p*64 + d];
    float uu    = g_u[p*64 + d];
    ulonglong2 Bv = *(const ulonglong2*)(g_Bc + p*16 + q*4);
    ulonglong2 Cv = *(const ulonglong2*)(g_Cc + p*16 + q*4);

    for (int l = 0; l < 128; l++) {
        size_t pn = p + (l < 127 ? stride : 0);
        float delta_n = g_delta[pn*64 + d];
        float uu_n    = g_u[pn*64 + d];
        ulonglong2 Bn = *(const ulonglong2*)(g_Bc + pn*16 + q*4);
        ulonglong2 Cn = *(const ulonglong2*)(g_Cc + pn*16 + q*4);

        float du = delta * uu;
        u64 du2 = pack2(du, du);
        u64 delta2 = pack2(delta, delta);
        u64 y2 = 0ull;

#define SSM_STEP2(t, bv, cv)                                       \
        {                                                          \
            u64 e2 = mul2(delta2, A22[t]);                         \
            float e0, e1; unpack2(e2, e0, e1);                     \
            u64 dA2 = pack2(fexp2(e0), fexp2(e1));                 \
            hs2[t] = fma2(dA2, hs2[t], mul2(du2, (bv)));           \
            y2 = fma2(hs2[t], (cv), y2);                           \
        }
        SSM_STEP2(0, Bv.x, Cv.x);
        SSM_STEP2(1, Bv.y, Cv.y);
#undef SSM_STEP2

        float ylo, yhi; unpack2(y2, ylo, yhi);
        float y = ylo + yhi;
        y += __shfl_xor_sync(0xffffffffu, y, 1);
        y += __shfl_xor_sync(0xffffffffu, y, 2);
        if (q == 0) yout[p*64 + d] = y;

        delta = delta_n; uu = uu_n;
        Bv = Bn; Cv = Cn;
        p = pn;
    }
}

// ---------------------------------------------------------------------------
// Combine + transpose (unchanged)
// ---------------------------------------------------------------------------
__global__ __launch_bounds__(256) void combine_kernel(const float* __restrict__ x,
                                                      const float* __restrict__ Dv,
                                                      float* __restrict__ out)
{
    __shared__ float s[32][33];
    int t    = blockIdx.x;
    int tile = t & 7;
    int bh   = t >> 3;
    int b    = bh >> 7;
    int h    = bh & 127;
    int c0   = (tile & 1) * 32;
    int w0   = (tile >> 1) * 32;
    size_t pbase = (size_t)bh * 128;

    {
        int row = threadIdx.x >> 3;
        int cg  = threadIdx.x & 7;
        size_t idx = (pbase + w0 + row)*64 + c0 + cg*4;
        float4 a = *(const float4*)(g_yh + idx);
        float4 v = *(const float4*)(g_yv + idx);
        s[row][cg*4+0] = a.x + v.x;
        s[row][cg*4+1] = a.y + v.y;
        s[row][cg*4+2] = a.z + v.z;
        s[row][cg*4+3] = a.w + v.w;
    }
    __syncthreads();

    int tx = threadIdx.x & 31;
    int ty = threadIdx.x >> 5;
    #pragma unroll
    for (int i = 0; i < 4; i++) {
        int ci = ty + i*8;
        int c  = c0 + ci;
        size_t xi = (((size_t)(b*64 + c))*128 + h)*128 + w0 + tx;
        out[xi] = s[tx][ci] + 2.f * Dv[c] * x[xi];
    }
}

// ---------------------------------------------------------------------------
extern "C" void kernel_launch(void* const* d_in, const int* in_sizes, int n_in,
                              void* d_out, int out_size)
{
    const float* x     = (const float*)d_in[0];   // [4,64,128,128]
    const float* A_log = (const float*)d_in[1];   // [64,16]
    const float* Dv    = (const float*)d_in[2];   // [64]
    const float* xw    = (const float*)d_in[3];   // [36,64]
    const float* dtw   = (const float*)d_in[4];   // [64,4]
    const float* dtb   = (const float*)d_in[5];   // [64]
    float* out = (float*)d_out;

    proj_kernel<<<NB*NH*2, 128>>>(x, xw, dtw, dtb);
    scan_kernel<<<1024, 256>>>(A_log);
    combine_kernel<<<NB*NH*8, 256>>>(x, Dv, out);
}

// round 11
// speedup vs baseline: 1.0242x; 1.0242x over previous
#include <cuda_runtime.h>
#include <cuda_bf16.h>

// Problem constants
#define NB 4
#define NC 64
#define NH 128
#define NW 128
#define NN 16
#define NPIX (NB*NH*NW)   // 65536 pixels

typedef unsigned long long u64;

// Scratch (allocation-free rule: __device__ globals)
static __device__ float g_delta[(size_t)NPIX*64];   // [p][c]
static __device__ float g_u[(size_t)NPIX*64];       // [p][c]
static __device__ float g_Bc[(size_t)NPIX*16];      // [p][n]
static __device__ float g_Cc[(size_t)NPIX*16];      // [p][n]
static __device__ float g_yh[(size_t)NPIX*64];      // [p][c]
static __device__ float g_yv[(size_t)NPIX*64];      // [p][c]

__device__ __forceinline__ float fexp2(float x) {
    float r;
    asm("ex2.approx.f32 %0, %1;" : "=f"(r) : "f"(x));
    return r;
}
__device__ __forceinline__ u64 pack2(float lo, float hi) {
    u64 r; asm("mov.b64 %0, {%1, %2};" : "=l"(r) : "f"(lo), "f"(hi)); return r;
}
__device__ __forceinline__ void unpack2(u64 v, float& lo, float& hi) {
    asm("mov.b64 {%0, %1}, %2;" : "=f"(lo), "=f"(hi) : "l"(v));
}
__device__ __forceinline__ u64 fma2(u64 a, u64 b, u64 c) {
    u64 d; asm("fma.rn.f32x2 %0, %1, %2, %3;" : "=l"(d) : "l"(a), "l"(b), "l"(c)); return d;
}
__device__ __forceinline__ u64 mul2(u64 a, u64 b) {
    u64 d; asm("mul.rn.f32x2 %0, %1, %2;" : "=l"(d) : "l"(a), "l"(b)); return d;
}

// ---------------------------------------------------------------------------
// Projection v6: grid = 512 rows x 2 output-halves; 128-thread blocks, 7/SM
// => grid 1024 in one wave. Block (bh, og) computes outputs [48og, 48og+48).
// Weights stored [o_local][k] so one LDS.64 fetches w for TWO adjacent k.
// Thread (ty 0..7, tx 0..15): 6 outs x 4 pixel-pairs, 24 f32x2 accumulators.
// ---------------------------------------------------------------------------
#define WK_STRIDE 66    // s_wt row pad ([o_local][k]), even => 8B aligned
#define X_STRIDE  130   // s_x  row pad ([k][pix]), even => 8B aligned

__global__ __launch_bounds__(128, 7) void proj_kernel(const float* __restrict__ x,
                                                      const float* __restrict__ xw,   // [36,64]
                                                      const float* __restrict__ dtw,  // [64,4]
                                                      const float* __restrict__ dtb)  // [64]
{
    __shared__ __align__(16) float s_wt[48*WK_STRIDE];  // [o_local][k]; reused as staging
    __shared__ __align__(16) float s_x[32*X_STRIDE];    // [k-half][pix]
    __shared__ float s_bias[64];

    int blk = blockIdx.x;          // 0..1023
    int bh  = blk >> 1;            // row 0..511
    int og  = blk & 1;             // output half
    int b   = bh >> 7;
    int h   = bh & 127;
    int tid = threadIdx.x;
    int tx  = tid & 15;            // pixel-pair group
    int ty  = tid >> 4;            // 0..7

    // Fold weights for this block's 48 output rows, stored [o_local][k].
    for (int i = tid; i < 48*64; i += 128) {
        int rl = i >> 6, c = i & 63;
        int r  = og*48 + rl;
        float v;
        if (r < 64) {
            v = dtw[r*4+0]*xw[0*64+c] + dtw[r*4+1]*xw[1*64+c]
              + dtw[r*4+2]*xw[2*64+c] + dtw[r*4+3]*xw[3*64+c];
        } else {
            v = xw[(r - 60)*64 + c];
        }
        s_wt[rl*WK_STRIDE + c] = v;
    }
    if (tid < 64) s_bias[tid] = dtb[tid];

    size_t pbase = (size_t)bh * 128;

    u64 acc2[6][4];
    #pragma unroll
    for (int i = 0; i < 6; i++)
        #pragma unroll
        for (int jp = 0; jp < 4; jp++) acc2[i][jp] = 0ull;

    for (int half = 0; half < 2; half++) {
        __syncthreads();   // half 0: also covers weight-fold completion
        // Load x tile: 32 channels x 128 pixels, coalesced rows
        #pragma unroll
        for (int it = 0; it < 32; it++) {
            int idx = it*128 + tid;
            int cl  = idx >> 7;      // 0..31
            int w   = idx & 127;
            s_x[cl*X_STRIDE + w] =
                x[(((size_t)(b*64 + half*32 + cl))*128 + h)*128 + w];
        }
        __syncthreads();

        // og==0 block also emits the u transpose [p][c] (coalesced 128B rows)
        if (og == 0) {
            #pragma unroll
            for (int it = 0; it < 32; it++) {
                int idx = it*128 + tid;
                int pix = idx >> 5;
                int c   = idx & 31;
                g_u[(pbase + pix)*64 + half*32 + c] = s_x[c*X_STRIDE + pix];
            }
        }

        // GEMM mainloop: 16 double-k steps over this half's 32 channels.
        // Per step: 6 LDS.64 (w[o][k:k+2], warp-broadcast) + 8 LDS.64 (x)
        // feeding 48 FFMA2.
        #pragma unroll 4
        for (int ks = 0; ks < 16; ks++) {
            int k0 = half*32 + 2*ks;         // global k for weights
            int kx = 2*ks;                   // k within s_x tile
            u64 wA[6], wB[6];
            #pragma unroll
            for (int i = 0; i < 6; i++) {
                float2 wp = *(const float2*)(s_wt + (ty + 8*i)*WK_STRIDE + k0);
                wA[i] = pack2(wp.x, wp.x);
                wB[i] = pack2(wp.y, wp.y);
            }
            u64 xpA[4], xpB[4];
            #pragma unroll
            for (int jp = 0; jp < 4; jp++) {
                xpA[jp] = *(const u64*)(s_x + kx*X_STRIDE     + 2*tx + 32*jp);
                xpB[jp] = *(const u64*)(s_x + (kx+1)*X_STRIDE + 2*tx + 32*jp);
            }
            #pragma unroll
            for (int i = 0; i < 6; i++) {
                #pragma unroll
                for (int jp = 0; jp < 4; jp++) {
                    acc2[i][jp] = fma2(wA[i], xpA[jp], acc2[i][jp]);
                    acc2[i][jp] = fma2(wB[i], xpB[jp], acc2[i][jp]);
                }
            }
        }
    }

    __syncthreads();

    // Epilogue: 3 chunks of 16 outputs; stage [pix][j] in smem (reuse s_wt).
    float* s_st = s_wt;
    for (int cch = 0; cch < 3; cch++) {
        #pragma unroll
        for (int jp = 0; jp < 4; jp++) {
            #pragma unroll
            for (int ii = 0; ii < 2; ii++) {
                float lo, hi; unpack2(acc2[cch*2 + ii][jp], lo, hi);
                int pp = 2*tx + 32*jp;
                s_st[pp*17 + ty + 8*ii]       = lo;
                s_st[(pp + 1)*17 + ty + 8*ii] = hi;
            }
        }
        __syncthreads();
        #pragma unroll
        for (int it = 0; it < 16; it++) {
            int idx = it*128 + tid;
            int pix = idx >> 4;
            int j   = idx & 15;
            float v = s_st[pix*17 + j];
            int o   = og*48 + cch*16 + j;
            if (o < 64) {
                v += s_bias[o];
                v = (v > 15.f) ? v : __logf(1.f + __expf(v));   // softplus
                g_delta[(pbase + pix)*64 + o] = v;
            } else if (o < 80) {
                g_Bc[(pbase + pix)*16 + (o - 64)] = v;
            } else {
                g_Cc[(pbase + pix)*16 + (o - 80)] = v;
            }
        }
        __syncthreads();
    }
}

// ---------------------------------------------------------------------------
// Scan (reverted to the proven R7 half-split): thread = (sequence, channel,
// half-of-states); packed f32x2 updates, software-pipelined loads, 1 shfl.
// Blocks 0..511 horizontal, 512..1023 vertical; 128 threads (64 ch x 2).
// ---------------------------------------------------------------------------
__global__ __launch_bounds__(128) void scan_kernel(const float* __restrict__ A_log)
{
    int tid  = threadIdx.x;
    int d    = tid >> 1;          // channel 0..63
    int half = tid & 1;           // state group (0: n=0..7, 1: n=8..15)
    int blk  = blockIdx.x;        // 0..1023
    int dir  = blk >> 9;          // 0 = H, 1 = V
    int s    = blk & 511;
    int b    = s >> 7;
    int rc   = s & 127;

    size_t pix0;
    int stride;
    float* __restrict__ yout;
    if (dir == 0) { pix0 = ((size_t)(b*128 + rc))*128; stride = 1;   yout = g_yh; }
    else          { pix0 = (size_t)b*16384 + rc;       stride = 128; yout = g_yv; }

    u64 A22[4];
    #pragma unroll
    for (int q = 0; q < 4; q++) {
        const float* ap = A_log + d*16 + half*8 + 2*q;
        float a0 = -__expf(ap[0]) * 1.4426950408889634f;
        float a1 = -__expf(ap[1]) * 1.4426950408889634f;
        A22[q] = pack2(a0, a1);
    }

    u64 hs2[4];
    #pragma unroll
    for (int q = 0; q < 4; q++) hs2[q] = 0ull;

    size_t p = pix0;

    float delta = g_delta[p*64 + d];
    float uu    = g_u[p*64 + d];
    ulonglong2 Bv = *(const ulonglong2*)(g_Bc + p*16 + half*8);
    ulonglong2 Cv = *(const ulonglong2*)(g_Cc + p*16 + half*8);
    ulonglong2 Bw = *(const ulonglong2*)(g_Bc + p*16 + half*8 + 4);
    ulonglong2 Cw = *(const ulonglong2*)(g_Cc + p*16 + half*8 + 4);

    for (int l = 0; l < 128; l++) {
        size_t pn = p + (l < 127 ? stride : 0);
        float delta_n = g_delta[pn*64 + d];
        float uu_n    = g_u[pn*64 + d];
        ulonglong2 Bn = *(const ulonglong2*)(g_Bc + pn*16 + half*8);
        ulonglong2 Cn = *(const ulonglong2*)(g_Cc + pn*16 + half*8);
        ulonglong2 Bm = *(const ulonglong2*)(g_Bc + pn*16 + half*8 + 4);
        ulonglong2 Cm = *(const ulonglong2*)(g_Cc + pn*16 + half*8 + 4);

        float du = delta * uu;
        u64 du2 = pack2(du, du);
        u64 delta2 = pack2(delta, delta);
        u64 y2 = 0ull;

#define SSM_STEP2(q, bv, cv)                                       \
        {                                                          \
            u64 e2 = mul2(delta2, A22[q]);                         \
            float e0, e1; unpack2(e2, e0, e1);                     \
            u64 dA2 = pack2(fexp2(e0), fexp2(e1));                 \
            hs2[q] = fma2(dA2, hs2[q], mul2(du2, (bv)));           \
            y2 = fma2(hs2[q], (cv), y2);                           \
        }
        SSM_STEP2(0, Bv.x, Cv.x);
        SSM_STEP2(1, Bv.y, Cv.y);
        SSM_STEP2(2, Bw.x, Cw.x);
        SSM_STEP2(3, Bw.y, Cw.y);
#undef SSM_STEP2

        float ylo, yhi; unpack2(y2, ylo, yhi);
        float y = ylo + yhi;
        y += __shfl_xor_sync(0xffffffffu, y, 1);
        if (half == 0) yout[p*64 + d] = y;

        delta = delta_n; uu = uu_n;
        Bv = Bn; Bw = Bm; Cv = Cn; Cw = Cm;
        p = pn;
    }
}

// ---------------------------------------------------------------------------
// Combine + transpose (unchanged)
// ---------------------------------------------------------------------------
__global__ __launch_bounds__(256) void combine_kernel(const float* __restrict__ x,
                                                      const float* __restrict__ Dv,
                                                      float* __restrict__ out)
{
    __shared__ float s[32][33];
    int t    = blockIdx.x;
    int tile = t & 7;
    int bh   = t >> 3;
    int b    = bh >> 7;
    int h    = bh & 127;
    int c0   = (tile & 1) * 32;
    int w0   = (tile >> 1) * 32;
    size_t pbase = (size_t)bh * 128;

    {
        int row = threadIdx.x >> 3;
        int cg  = threadIdx.x & 7;
        size_t idx = (pbase + w0 + row)*64 + c0 + cg*4;
        float4 a = *(const float4*)(g_yh + idx);
        float4 v = *(const float4*)(g_yv + idx);
        s[row][cg*4+0] = a.x + v.x;
        s[row][cg*4+1] = a.y + v.y;
        s[row][cg*4+2] = a.z + v.z;
        s[row][cg*4+3] = a.w + v.w;
    }
    __syncthreads();

    int tx = threadIdx.x & 31;
    int ty = threadIdx.x >> 5;
    #pragma unroll
    for (int i = 0; i < 4; i++) {
        int ci = ty + i*8;
        int c  = c0 + ci;
        size_t xi = (((size_t)(b*64 + c))*128 + h)*128 + w0 + tx;
        out[xi] = s[tx][ci] + 2.f * Dv[c] * x[xi];
    }
}

// ---------------------------------------------------------------------------
extern "C" void kernel_launch(void* const* d_in, const int* in_sizes, int n_in,
                              void* d_out, int out_size)
{
    const float* x     = (const float*)d_in[0];   // [4,64,128,128]
    const float* A_log = (const float*)d_in[1];   // [64,16]
    const float* Dv    = (const float*)d_in[2];   // [64]
    const float* xw    = (const float*)d_in[3];   // [36,64]
    const float* dtw   = (const float*)d_in[4];   // [64,4]
    const float* dtb   = (const float*)d_in[5];   // [64]
    float* out = (float*)d_out;

    proj_kernel<<<NB*NH*2, 128>>>(x, xw, dtw, dtb);
    scan_kernel<<<1024, 128>>>(A_log);
    combine_kernel<<<NB*NH*8, 256>>>(x, Dv, out);
}

// round 13
// speedup vs baseline: 1.1194x; 1.0929x over previous
#include <cuda_runtime.h>
#include <cuda_bf16.h>

// Problem constants
#define NB 4
#define NC 64
#define NH 128
#define NW 128
#define NN 16
#define NPIX (NB*NH*NW)   // 65536 pixels

typedef unsigned long long u64;

// Scratch (allocation-free rule: __device__ globals)
static __device__ float g_delta[(size_t)NPIX*64];   // [p][c]
static __device__ float g_u[(size_t)NPIX*64];       // [p][c]
static __device__ float g_Bc[(size_t)NPIX*16];      // [p][n]
static __device__ float g_Cc[(size_t)NPIX*16];      // [p][n]
static __device__ float g_yh[(size_t)NPIX*64];      // [p][c]
static __device__ float g_yv[(size_t)NPIX*64];      // [p][c]

__device__ __forceinline__ float fexp2(float x) {
    float r;
    asm("ex2.approx.f32 %0, %1;" : "=f"(r) : "f"(x));
    return r;
}
__device__ __forceinline__ u64 pack2(float lo, float hi) {
    u64 r; asm("mov.b64 %0, {%1, %2};" : "=l"(r) : "f"(lo), "f"(hi)); return r;
}
__device__ __forceinline__ void unpack2(u64 v, float& lo, float& hi) {
    asm("mov.b64 {%0, %1}, %2;" : "=f"(lo), "=f"(hi) : "l"(v));
}
__device__ __forceinline__ u64 fma2(u64 a, u64 b, u64 c) {
    u64 d; asm("fma.rn.f32x2 %0, %1, %2, %3;" : "=l"(d) : "l"(a), "l"(b), "l"(c)); return d;
}
__device__ __forceinline__ u64 mul2(u64 a, u64 b) {
    u64 d; asm("mul.rn.f32x2 %0, %1, %2;" : "=l"(d) : "l"(a), "l"(b)); return d;
}

// ---------------------------------------------------------------------------
// Projection v5 (reverted to the R9-profiled version, 46.8us): grid = 512
// rows x 2 output-halves; 128-thread blocks, 7/SM => grid 1024 in one wave.
// Block (bh, og) computes outputs [48og, 48og+48) for 128 pixels.
// Thread (ty 0..7, tx 0..15): 6 outs x 4 pixel-pairs = 24 f32x2 accumulators.
// ---------------------------------------------------------------------------
#define WT_STRIDE 52    // s_wt row pad ([k][48 outs])
#define X_STRIDE  130   // s_x  row pad ([k][128 pix]), even => 8B aligned

__global__ __launch_bounds__(128, 7) void proj_kernel(const float* __restrict__ x,
                                                      const float* __restrict__ xw,   // [36,64]
                                                      const float* __restrict__ dtw,  // [64,4]
                                                      const float* __restrict__ dtb)  // [64]
{
    __shared__ __align__(16) float s_wt[64*WT_STRIDE];  // [k 0..63][o_local]; reused as staging
    __shared__ __align__(16) float s_x[32*X_STRIDE];    // [k-half][pix]
    __shared__ float s_bias[64];

    int blk = blockIdx.x;          // 0..1023
    int bh  = blk >> 1;            // row 0..511
    int og  = blk & 1;             // output half
    int b   = bh >> 7;
    int h   = bh & 127;
    int tid = threadIdx.x;
    int tx  = tid & 15;            // pixel-pair group
    int ty  = tid >> 4;            // 0..7

    // Fold weights for this block's 48 output rows, stored [k][o_local].
    for (int i = tid; i < 48*64; i += 128) {
        int rl = i >> 6, c = i & 63;
        int r  = og*48 + rl;
        float v;
        if (r < 64) {
            v = dtw[r*4+0]*xw[0*64+c] + dtw[r*4+1]*xw[1*64+c]
              + dtw[r*4+2]*xw[2*64+c] + dtw[r*4+3]*xw[3*64+c];
        } else {
            v = xw[(r - 60)*64 + c];
        }
        s_wt[c*WT_STRIDE + rl] = v;
    }
    if (tid < 64) s_bias[tid] = dtb[tid];

    size_t pbase = (size_t)bh * 128;

    u64 acc2[6][4];
    #pragma unroll
    for (int i = 0; i < 6; i++)
        #pragma unroll
        for (int jp = 0; jp < 4; jp++) acc2[i][jp] = 0ull;

    for (int half = 0; half < 2; half++) {
        __syncthreads();   // half 0: also covers weight-fold completion
        // Load x tile: 32 channels x 128 pixels, coalesced rows
        #pragma unroll
        for (int it = 0; it < 32; it++) {
            int idx = it*128 + tid;
            int cl  = idx >> 7;      // 0..31
            int w   = idx & 127;
            s_x[cl*X_STRIDE + w] =
                x[(((size_t)(b*64 + half*32 + cl))*128 + h)*128 + w];
        }
        __syncthreads();

        // og==0 block also emits the u transpose [p][c] (coalesced 128B rows)
        if (og == 0) {
            #pragma unroll
            for (int it = 0; it < 32; it++) {
                int idx = it*128 + tid;
                int pix = idx >> 5;
                int c   = idx & 31;
                g_u[(pbase + pix)*64 + half*32 + c] = s_x[c*X_STRIDE + pix];
            }
        }

        // GEMM mainloop over this half's 32 channels (weight rows half*32+k)
        #pragma unroll 4
        for (int k = 0; k < 32; k++) {
            const float* wrow = s_wt + (half*32 + k)*WT_STRIDE + ty;
            u64 w2[6];
            #pragma unroll
            for (int i = 0; i < 6; i++) {
                float wv = wrow[8*i];
                w2[i] = pack2(wv, wv);
            }
            u64 xp[4];
            #pragma unroll
            for (int jp = 0; jp < 4; jp++)
                xp[jp] = *(const u64*)(s_x + k*X_STRIDE + 2*tx + 32*jp);
            #pragma unroll
            for (int i = 0; i < 6; i++)
                #pragma unroll
                for (int jp = 0; jp < 4; jp++)
                    acc2[i][jp] = fma2(w2[i], xp[jp], acc2[i][jp]);
        }
    }

    __syncthreads();

    // Epilogue: 3 chunks of 16 outputs; stage [pix][j] in smem (reuse s_wt).
    float* s_st = s_wt;
    for (int cch = 0; cch < 3; cch++) {
        #pragma unroll
        for (int jp = 0; jp < 4; jp++) {
            #pragma unroll
            for (int ii = 0; ii < 2; ii++) {
                float lo, hi; unpack2(acc2[cch*2 + ii][jp], lo, hi);
                int pp = 2*tx + 32*jp;
                s_st[pp*17 + ty + 8*ii]       = lo;
                s_st[(pp + 1)*17 + ty + 8*ii] = hi;
            }
        }
        __syncthreads();
        #pragma unroll
        for (int it = 0; it < 16; it++) {
            int idx = it*128 + tid;
            int pix = idx >> 4;
            int j   = idx & 15;
            float v = s_st[pix*17 + j];
            int o   = og*48 + cch*16 + j;
            if (o < 64) {
                v += s_bias[o];
                v = (v > 15.f) ? v : __logf(1.f + __expf(v));   // softplus
                g_delta[(pbase + pix)*64 + o] = v;
            } else if (o < 80) {
                g_Bc[(pbase + pix)*16 + (o - 64)] = v;
            } else {
                g_Cc[(pbase + pix)*16 + (o - 80)] = v;
            }
        }
        __syncthreads();
    }
}

// ---------------------------------------------------------------------------
// Scan v5: half-split (proven layout) + DEPTH-2 software pipeline.
// Thread = (sequence, channel d, half of 16 states). 128-thread blocks,
// 1024 blocks (512 H + 512 V). Loads for iteration l+2 are issued before
// computing iteration l, doubling the latency-hiding window.
// ---------------------------------------------------------------------------
struct ScanBuf {
    float delta, uu;
    ulonglong2 Bv, Cv, Bw, Cw;
};

__device__ __forceinline__ void scan_load(ScanBuf& t, size_t p, int d, int half)
{
    t.delta = g_delta[p*64 + d];
    t.uu    = g_u[p*64 + d];
    t.Bv = *(const ulonglong2*)(g_Bc + p*16 + half*8);
    t.Cv = *(const ulonglong2*)(g_Cc + p*16 + half*8);
    t.Bw = *(const ulonglong2*)(g_Bc + p*16 + half*8 + 4);
    t.Cw = *(const ulonglong2*)(g_Cc + p*16 + half*8 + 4);
}

__global__ __launch_bounds__(128) void scan_kernel(const float* __restrict__ A_log)
{
    int tid  = threadIdx.x;
    int d    = tid >> 1;          // channel 0..63
    int half = tid & 1;           // state group (0: n=0..7, 1: n=8..15)
    int blk  = blockIdx.x;        // 0..1023
    int dir  = blk >> 9;          // 0 = H, 1 = V
    int s    = blk & 511;
    int b    = s >> 7;
    int rc   = s & 127;

    size_t pix0;
    int stride;
    float* __restrict__ yout;
    if (dir == 0) { pix0 = ((size_t)(b*128 + rc))*128; stride = 1;   yout = g_yh; }
    else          { pix0 = (size_t)b*16384 + rc;       stride = 128; yout = g_yv; }

    u64 A22[4];
    #pragma unroll
    for (int q = 0; q < 4; q++) {
        const float* ap = A_log + d*16 + half*8 + 2*q;
        float a0 = -__expf(ap[0]) * 1.4426950408889634f;
        float a1 = -__expf(ap[1]) * 1.4426950408889634f;
        A22[q] = pack2(a0, a1);
    }

    u64 hs2[4];
    #pragma unroll
    for (int q = 0; q < 4; q++) hs2[q] = 0ull;

    ScanBuf b0, b1;
    scan_load(b0, pix0, d, half);
    scan_load(b1, pix0 + stride, d, half);

#define SSM_BODY(buf, p)                                               \
    {                                                                  \
        float du = buf.delta * buf.uu;                                 \
        u64 du2 = pack2(du, du);                                       \
        u64 delta2 = pack2(buf.delta, buf.delta);                      \
        u64 y2 = 0ull;                                                 \
        {                                                              \
            u64 e2 = mul2(delta2, A22[0]);                             \
            float e0, e1; unpack2(e2, e0, e1);                         \
            u64 dA2 = pack2(fexp2(e0), fexp2(e1));                     \
            hs2[0] = fma2(dA2, hs2[0], mul2(du2, buf.Bv.x));           \
            y2 = fma2(hs2[0], buf.Cv.x, y2);                           \
        }                                                              \
        {                                                              \
            u64 e2 = mul2(delta2, A22[1]);                             \
            float e0, e1; unpack2(e2, e0, e1);                         \
            u64 dA2 = pack2(fexp2(e0), fexp2(e1));                     \
            hs2[1] = fma2(dA2, hs2[1], mul2(du2, buf.Bv.y));           \
            y2 = fma2(hs2[1], buf.Cv.y, y2);                           \
        }                                                              \
        {                                                              \
            u64 e2 = mul2(delta2, A22[2]);                             \
            float e0, e1; unpack2(e2, e0, e1);                         \
            u64 dA2 = pack2(fexp2(e0), fexp2(e1));                     \
            hs2[2] = fma2(dA2, hs2[2], mul2(du2, buf.Bw.x));           \
            y2 = fma2(hs2[2], buf.Cw.x, y2);                           \
        }                                                              \
        {                                                              \
            u64 e2 = mul2(delta2, A22[3]);                             \
            float e0, e1; unpack2(e2, e0, e1);                         \
            u64 dA2 = pack2(fexp2(e0), fexp2(e1));                     \
            hs2[3] = fma2(dA2, hs2[3], mul2(du2, buf.Bw.y));           \
            y2 = fma2(hs2[3], buf.Cw.y, y2);                           \
        }                                                              \
        float ylo, yhi; unpack2(y2, ylo, yhi);                         \
        float y = ylo + yhi;                                           \
        y += __shfl_xor_sync(0xffffffffu, y, 1);                       \
        if (half == 0) yout[(p)*64 + d] = y;                           \
    }

    size_t p = pix0;
    for (int l = 0; l < 128; l += 2) {
        // prefetch iters l+2 and l+3 (clamped in-bounds on the tail)
        int i2 = l + 2 < 128 ? l + 2 : 127;
        int i3 = l + 3 < 128 ? l + 3 : 127;
        ScanBuf t0, t1;
        scan_load(t0, pix0 + (size_t)i2*stride, d, half);
        SSM_BODY(b0, p);
        scan_load(t1, pix0 + (size_t)i3*stride, d, half);
        SSM_BODY(b1, p + stride);
        b0 = t0; b1 = t1;
        p += 2*stride;
    }
#undef SSM_BODY
}

// ---------------------------------------------------------------------------
// Combine + transpose (unchanged)
// ---------------------------------------------------------------------------
__global__ __launch_bounds__(256) void combine_kernel(const float* __restrict__ x,
                                                      const float* __restrict__ Dv,
                                                      float* __restrict__ out)
{
    __shared__ float s[32][33];
    int t    = blockIdx.x;
    int tile = t & 7;
    int bh   = t >> 3;
    int b    = bh >> 7;
    int h    = bh & 127;
    int c0   = (tile & 1) * 32;
    int w0   = (tile >> 1) * 32;
    size_t pbase = (size_t)bh * 128;

    {
        int row = threadIdx.x >> 3;
        int cg  = threadIdx.x & 7;
        size_t idx = (pbase + w0 + row)*64 + c0 + cg*4;
        float4 a = *(const float4*)(g_yh + idx);
        float4 v = *(const float4*)(g_yv + idx);
        s[row][cg*4+0] = a.x + v.x;
        s[row][cg*4+1] = a.y + v.y;
        s[row][cg*4+2] = a.z + v.z;
        s[row][cg*4+3] = a.w + v.w;
    }
    __syncthreads();

    int tx = threadIdx.x & 31;
    int ty = threadIdx.x >> 5;
    #pragma unroll
    for (int i = 0; i < 4; i++) {
        int ci = ty + i*8;
        int c  = c0 + ci;
        size_t xi = (((size_t)(b*64 + c))*128 + h)*128 + w0 + tx;
        out[xi] = s[tx][ci] + 2.f * Dv[c] * x[xi];
    }
}

// ---------------------------------------------------------------------------
extern "C" void kernel_launch(void* const* d_in, const int* in_sizes, int n_in,
                              void* d_out, int out_size)
{
    const float* x     = (const float*)d_in[0];   // [4,64,128,128]
    const float* A_log = (const float*)d_in[1];   // [64,16]
    const float* Dv    = (const float*)d_in[2];   // [64]
    const float* xw    = (const float*)d_in[3];   // [36,64]
    const float* dtw   = (const float*)d_in[4];   // [64,4]
    const float* dtb   = (const float*)d_in[5];   // [64]
    float* out = (float*)d_out;

    proj_kernel<<<NB*NH*2, 128>>>(x, xw, dtw, dtb);
    scan_kernel<<<1024, 128>>>(A_log);
    combine_kernel<<<NB*NH*8, 256>>>(x, Dv, out);
}

// round 15
// speedup vs baseline: 1.3332x; 1.1910x over previous
#include <cuda_runtime.h>
#include <cuda_bf16.h>

// Problem constants
#define NB 4
#define NC 64
#define NH 128
#define NW 128
#define NN 16
#define NPIX (NB*NH*NW)   // 65536 pixels

typedef unsigned long long u64;

// Scratch (allocation-free rule: __device__ globals)
static __device__ float g_delta[(size_t)NPIX*64];   // [p][c]
static __device__ float g_u[(size_t)NPIX*64];       // [p][c]
static __device__ float g_Bc[(size_t)NPIX*16];      // [p][n]
static __device__ float g_Cc[(size_t)NPIX*16];      // [p][n]
static __device__ float g_yh[(size_t)NPIX*64];      // [p][c]
static __device__ float g_yv[(size_t)NPIX*64];      // [p][c]

__device__ __forceinline__ float fexp2(float x) {
    float r;
    asm("ex2.approx.f32 %0, %1;" : "=f"(r) : "f"(x));
    return r;
}
__device__ __forceinline__ u64 pack2(float lo, float hi) {
    u64 r; asm("mov.b64 %0, {%1, %2};" : "=l"(r) : "f"(lo), "f"(hi)); return r;
}
__device__ __forceinline__ void unpack2(u64 v, float& lo, float& hi) {
    asm("mov.b64 {%0, %1}, %2;" : "=f"(lo), "=f"(hi) : "l"(v));
}
__device__ __forceinline__ u64 fma2(u64 a, u64 b, u64 c) {
    u64 d; asm("fma.rn.f32x2 %0, %1, %2, %3;" : "=l"(d) : "l"(a), "l"(b), "l"(c)); return d;
}
__device__ __forceinline__ u64 mul2(u64 a, u64 b) {
    u64 d; asm("mul.rn.f32x2 %0, %1, %2;" : "=l"(d) : "l"(a), "l"(b)); return d;
}

// ---------------------------------------------------------------------------
// Projection v5 (unchanged, measured 47.3us): grid = 512 rows x 2 halves;
// 128-thread blocks, 7/SM => grid 1024 in one wave.
// ---------------------------------------------------------------------------
#define WT_STRIDE 52    // s_wt row pad ([k][48 outs])
#define X_STRIDE  130   // s_x  row pad ([k][128 pix]), even => 8B aligned

__global__ __launch_bounds__(128, 7) void proj_kernel(const float* __restrict__ x,
                                                      const float* __restrict__ xw,   // [36,64]
                                                      const float* __restrict__ dtw,  // [64,4]
                                                      const float* __restrict__ dtb)  // [64]
{
    __shared__ __align__(16) float s_wt[64*WT_STRIDE];  // [k][o_local]; reused as staging
    __shared__ __align__(16) float s_x[32*X_STRIDE];    // [k-half][pix]
    __shared__ float s_bias[64];

    int blk = blockIdx.x;          // 0..1023
    int bh  = blk >> 1;            // row 0..511
    int og  = blk & 1;             // output half
    int b   = bh >> 7;
    int h   = bh & 127;
    int tid = threadIdx.x;
    int tx  = tid & 15;            // pixel-pair group
    int ty  = tid >> 4;            // 0..7

    for (int i = tid; i < 48*64; i += 128) {
        int rl = i >> 6, c = i & 63;
        int r  = og*48 + rl;
        float v;
        if (r < 64) {
            v = dtw[r*4+0]*xw[0*64+c] + dtw[r*4+1]*xw[1*64+c]
              + dtw[r*4+2]*xw[2*64+c] + dtw[r*4+3]*xw[3*64+c];
        } else {
            v = xw[(r - 60)*64 + c];
        }
        s_wt[c*WT_STRIDE + rl] = v;
    }
    if (tid < 64) s_bias[tid] = dtb[tid];

    size_t pbase = (size_t)bh * 128;

    u64 acc2[6][4];
    #pragma unroll
    for (int i = 0; i < 6; i++)
        #pragma unroll
        for (int jp = 0; jp < 4; jp++) acc2[i][jp] = 0ull;

    for (int half = 0; half < 2; half++) {
        __syncthreads();
        #pragma unroll
        for (int it = 0; it < 32; it++) {
            int idx = it*128 + tid;
            int cl  = idx >> 7;
            int w   = idx & 127;
            s_x[cl*X_STRIDE + w] =
                x[(((size_t)(b*64 + half*32 + cl))*128 + h)*128 + w];
        }
        __syncthreads();

        if (og == 0) {
            #pragma unroll
            for (int it = 0; it < 32; it++) {
                int idx = it*128 + tid;
                int pix = idx >> 5;
                int c   = idx & 31;
                g_u[(pbase + pix)*64 + half*32 + c] = s_x[c*X_STRIDE + pix];
            }
        }

        #pragma unroll 4
        for (int k = 0; k < 32; k++) {
            const float* wrow = s_wt + (half*32 + k)*WT_STRIDE + ty;
            u64 w2[6];
            #pragma unroll
            for (int i = 0; i < 6; i++) {
                float wv = wrow[8*i];
                w2[i] = pack2(wv, wv);
            }
            u64 xp[4];
            #pragma unroll
            for (int jp = 0; jp < 4; jp++)
                xp[jp] = *(const u64*)(s_x + k*X_STRIDE + 2*tx + 32*jp);
            #pragma unroll
            for (int i = 0; i < 6; i++)
                #pragma unroll
                for (int jp = 0; jp < 4; jp++)
                    acc2[i][jp] = fma2(w2[i], xp[jp], acc2[i][jp]);
        }
    }

    __syncthreads();

    float* s_st = s_wt;
    for (int cch = 0; cch < 3; cch++) {
        #pragma unroll
        for (int jp = 0; jp < 4; jp++) {
            #pragma unroll
            for (int ii = 0; ii < 2; ii++) {
                float lo, hi; unpack2(acc2[cch*2 + ii][jp], lo, hi);
                int pp = 2*tx + 32*jp;
                s_st[pp*17 + ty + 8*ii]       = lo;
                s_st[(pp + 1)*17 + ty + 8*ii] = hi;
            }
        }
        __syncthreads();
        #pragma unroll
        for (int it = 0; it < 16; it++) {
            int idx = it*128 + tid;
            int pix = idx >> 4;
            int j   = idx & 15;
            float v = s_st[pix*17 + j];
            int o   = og*48 + cch*16 + j;
            if (o < 64) {
                v += s_bias[o];
                v = (v > 15.f) ? v : __logf(1.f + __expf(v));   // softplus
                g_delta[(pbase + pix)*64 + o] = v;
            } else if (o < 80) {
                g_Bc[(pbase + pix)*16 + (o - 64)] = v;
            } else {
                g_Cc[(pbase + pix)*16 + (o - 80)] = v;
            }
        }
        __syncthreads();
    }
}

// ---------------------------------------------------------------------------
// Scan v6: half-split layout (proven), depth-1 delta/u prefetch, and B/C
// staged through double-buffered shared memory. Per 16-iter chunk, one
// cooperative LDG.128+STS.128 per thread replaces 64 redundant in-loop
// LDG.128s; in-loop B/C reads become broadcast LDS.128.
// One sequence per 128-thread block; blocks 0..511 H, 512..1023 V.
// ---------------------------------------------------------------------------
__global__ __launch_bounds__(128) void scan_kernel(const float* __restrict__ A_log)
{
    __shared__ __align__(16) float s_B[2][16*16];   // [buf][iter][n]
    __shared__ __align__(16) float s_C[2][16*16];

    int tid  = threadIdx.x;
    int d    = tid >> 1;          // channel 0..63
    int half = tid & 1;           // state group (0: n=0..7, 1: n=8..15)
    int blk  = blockIdx.x;        // 0..1023
    int dir  = blk >> 9;          // 0 = H, 1 = V
    int s    = blk & 511;
    int b    = s >> 7;
    int rc   = s & 127;

    size_t pix0;
    int stride;
    float* __restrict__ yout;
    if (dir == 0) { pix0 = ((size_t)(b*128 + rc))*128; stride = 1;   yout = g_yh; }
    else          { pix0 = (size_t)b*16384 + rc;       stride = 128; yout = g_yv; }

    u64 A22[4];
    #pragma unroll
    for (int q = 0; q < 4; q++) {
        const float* ap = A_log + d*16 + half*8 + 2*q;
        float a0 = -__expf(ap[0]) * 1.4426950408889634f;
        float a1 = -__expf(ap[1]) * 1.4426950408889634f;
        A22[q] = pack2(a0, a1);
    }

    u64 hs2[4];
    #pragma unroll
    for (int q = 0; q < 4; q++) hs2[q] = 0ull;

    // Cooperative-load decomposition: threads 0..63 -> B, 64..127 -> C;
    // within each half: iter i = (t&63)>>2, float4 lane j = t&3.
    int ci = (tid & 63) >> 2;
    int cj = tid & 3;
    const float* csrc_base = (tid < 64) ? g_Bc : g_Cc;

    // delta/u depth-1 prefetch registers
    float delta = g_delta[pix0*64 + d];
    float uu    = g_u[pix0*64 + d];

    for (int c = 0; c < 8; c++) {
        // Stage chunk c's B/C (iterations c*16 .. c*16+15) into buffer c&1
        {
            size_t pp = pix0 + (size_t)(c*16 + ci)*stride;
            float4 v = *(const float4*)(csrc_base + pp*16 + cj*4);
            float* dst = ((tid < 64) ? s_B[c & 1] : s_C[c & 1]) + ci*16 + cj*4;
            *(float4*)dst = v;
        }
        __syncthreads();

        const float* bbuf = s_B[c & 1];
        const float* cbuf = s_C[c & 1];

        #pragma unroll
        for (int i = 0; i < 16; i++) {
            int l = c*16 + i;
            size_t p = pix0 + (size_t)l*stride;
            // prefetch next iteration's delta/u (clamped on the tail)
            int ln = (l < 127) ? l + 1 : 127;
            size_t pn = pix0 + (size_t)ln*stride;
            float delta_n = g_delta[pn*64 + d];
            float uu_n    = g_u[pn*64 + d];

            // B/C for this half from smem (broadcast, conflict-free)
            ulonglong2 Bv = *(const ulonglong2*)(bbuf + i*16 + half*8);
            ulonglong2 Cv = *(const ulonglong2*)(cbuf + i*16 + half*8);

            float du = delta * uu;
            u64 du2 = pack2(du, du);
            u64 delta2 = pack2(delta, delta);
            u64 y2 = 0ull;

#define SSM_STEP2(q, bv, cv)                                       \
            {                                                      \
                u64 e2 = mul2(delta2, A22[q]);                     \
                float e0, e1; unpack2(e2, e0, e1);                 \
                u64 dA2 = pack2(fexp2(e0), fexp2(e1));             \
                hs2[q] = fma2(dA2, hs2[q], mul2(du2, (bv)));       \
                y2 = fma2(hs2[q], (cv), y2);                       \
            }
            {
                SSM_STEP2(0, Bv.x, Cv.x);
                SSM_STEP2(1, Bv.y, Cv.y);
            }
            {
                ulonglong2 Bw = *(const ulonglong2*)(bbuf + i*16 + half*8 + 4);
                ulonglong2 Cw = *(const ulonglong2*)(cbuf + i*16 + half*8 + 4);
                SSM_STEP2(2, Bw.x, Cw.x);
                SSM_STEP2(3, Bw.y, Cw.y);
            }
#undef SSM_STEP2

            float ylo, yhi; unpack2(y2, ylo, yhi);
            float y = ylo + yhi;
            y += __shfl_xor_sync(0xffffffffu, y, 1);
            if (half == 0) yout[p*64 + d] = y;

            delta = delta_n; uu = uu_n;
        }
    }
}

// ---------------------------------------------------------------------------
// Combine + transpose (unchanged)
// ---------------------------------------------------------------------------
__global__ __launch_bounds__(256) void combine_kernel(const float* __restrict__ x,
                                                      const float* __restrict__ Dv,
                                                      float* __restrict__ out)
{
    __shared__ float s[32][33];
    int t    = blockIdx.x;
    int tile = t & 7;
    int bh   = t >> 3;
    int b    = bh >> 7;
    int h    = bh & 127;
    int c0   = (tile & 1) * 32;
    int w0   = (tile >> 1) * 32;
    size_t pbase = (size_t)bh * 128;

    {
        int row = threadIdx.x >> 3;
        int cg  = threadIdx.x & 7;
        size_t idx = (pbase + w0 + row)*64 + c0 + cg*4;
        float4 a = *(const float4*)(g_yh + idx);
        float4 v = *(const float4*)(g_yv + idx);
        s[row][cg*4+0] = a.x + v.x;
        s[row][cg*4+1] = a.y + v.y;
        s[row][cg*4+2] = a.z + v.z;
        s[row][cg*4+3] = a.w + v.w;
    }
    __syncthreads();

    int tx = threadIdx.x & 31;
    int ty = threadIdx.x >> 5;
    #pragma unroll
    for (int i = 0; i < 4; i++) {
        int ci = ty + i*8;
        int c  = c0 + ci;
        size_t xi = (((size_t)(b*64 + c))*128 + h)*128 + w0 + tx;
        out[xi] = s[tx][ci] + 2.f * Dv[c] * x[xi];
    }
}

// ---------------------------------------------------------------------------
extern "C" void kernel_launch(void* const* d_in, const int* in_sizes, int n_in,
                              void* d_out, int out_size)
{
    const float* x     = (const float*)d_in[0];   // [4,64,128,128]
    const float* A_log = (const float*)d_in[1];   // [64,16]
    const float* Dv    = (const float*)d_in[2];   // [64]
    const float* xw    = (const float*)d_in[3];   // [36,64]
    const float* dtw   = (const float*)d_in[4];   // [64,4]
    const float* dtb   = (const float*)d_in[5];   // [64]
    float* out = (float*)d_out;

    proj_kernel<<<NB*NH*2, 128>>>(x, xw, dtw, dtb);
    scan_kernel<<<1024, 128>>>(A_log);
    combine_kernel<<<NB*NH*8, 256>>>(x, Dv, out);
}